// round 15
// baseline (speedup 1.0000x reference)
#include <cuda_runtime.h>

#define NT   25
#define NMAX 50176
#define EMAX 250112
#define GRID 148
#define THREADS 768       // 24 warps/SM, 85-reg budget

__device__ float g_h [NMAX * 16];
__device__ float g_h2[NMAX * 16];
__device__ int   g_rowcnt[NMAX];
__device__ int   g_rowptr[NMAX + 1];
__device__ int   g_wcur  [NMAX];
__device__ int   g_bsum[512];
__device__ int4  g_epack[EMAX];       // CSR-ordered {etype, src, ef0_bits, ef1_bits}
__device__ float g_pool[64 * 16];
__device__ int   g_pcnt[64];

// ---- software grid barrier (sense-reversing)
__device__ unsigned g_count = 0;
__device__ volatile unsigned g_gen = 0;

__device__ __forceinline__ void grid_barrier() {
    __syncthreads();
    if (threadIdx.x == 0) {
        __threadfence();
        unsigned my = g_gen;
        if (atomicAdd(&g_count, 1u) == GRID - 1) {
            g_count = 0;
            __threadfence();
            g_gen = my + 1;
        } else {
            while (g_gen == my) __nanosleep(64);
        }
        __threadfence();
    }
    __syncthreads();
}

struct KParams {
    const float*  x;
    const float2* ef;
    const int *etype, *esrc, *edst, *ctype, *bids;
    const float *emb[3], *wh[3], *bh[3], *wg[3], *bg[3], *root[3], *bias[3];
    float* out;
    int N, E, B;
};

// load this half's contiguous x slice: broadcast loads (no shuffles)
template <int IN>
__device__ __forceinline__ void load_xhalf(const float* __restrict__ xin,
                                           int row, int half, float* xk) {
    const float* p = xin + row * 16 + half * (IN / 2);
    if constexpr (IN == 16) {                 // 8 floats, 32B-aligned
        float4 a = __ldg((const float4*)p);
        float4 b = __ldg((const float4*)(p + 4));
        xk[0] = a.x; xk[1] = a.y; xk[2] = a.z; xk[3] = a.w;
        xk[4] = b.x; xk[5] = b.y; xk[6] = b.z; xk[7] = b.w;
    } else {                                  // 5 floats, same-line broadcasts
#pragma unroll
        for (int k = 0; k < IN / 2; k++) xk[k] = __ldg(p + k);
    }
}

// ---- fused layer, 32-lane group per node, i-dim split across warp halves.
// NO shuffles in the edge loop: x half-rows loaded directly (broadcast LDG).
// w[t,i,o](ef) = relu(emb * (ef0*wh0 + ef1*wh1 + bh) + (ef0*wg0 + ef1*wg1 + bg))
template <int IN, int OUT, bool POOL>
__device__ __forceinline__ void do_layer(
    const float* __restrict__ xin, float* __restrict__ hout,
    const float* __restrict__ emb, const float* __restrict__ wh,
    const float* __restrict__ bh,  const float* __restrict__ wg,
    const float* __restrict__ bg,  const float* __restrict__ root,
    const float* __restrict__ bias,
    const int* __restrict__ ctype, const int* __restrict__ bids,
    float2* sE, float* s_root, float* s_bias,
    float* s_pool, int* s_cnt, int N, int B)
{
    constexpr int D     = IN * OUT;
    constexpr int HIN   = IN / 2;                 // 8 or 5
    constexpr int HPAIR = HIN / 2;                // 4 or 2
    constexpr bool TAIL = (HIN & 1) != 0;         // IN=10 -> one tail step
    constexpr int SLOT  = (IN == 16) ? 5 : 3;     // padded float2 slots per (t,o,half)
    int tid = threadIdx.x;

    // emb table: sE[((t*16+o)*2+half)*SLOT + s] = (emb[t, half*HIN+2s, o], emb[t, half*HIN+2s+1, o])
    for (int j = tid; j < NT * 32 * SLOT; j += THREADS) {
        int s  = j % SLOT;
        int rh = j / SLOT;
        int hf = rh & 1;
        int o  = (rh >> 1) & 15;
        int t  = rh >> 5;
        int i0 = 2 * s;
        float e0 = 0.f, e1 = 0.f;
        if (o < OUT && i0 < HIN)     e0 = __ldg(&emb[t * D + (hf * HIN + i0)     * OUT + o]);
        if (o < OUT && i0 + 1 < HIN) e1 = __ldg(&emb[t * D + (hf * HIN + i0 + 1) * OUT + o]);
        sE[j] = make_float2(e0, e1);
    }
    if (tid < D)   s_root[tid] = __ldg(&root[tid]);
    if (tid < OUT) s_bias[tid] = __ldg(&bias[tid]);
    if (POOL) {
        if (tid < 128) s_pool[tid] = 0.f;
        if (tid < 8)   s_cnt[tid]  = 0;
    }
    __syncthreads();

    int o    = tid & 15;
    int half = (tid >> 4) & 1;
    int oc   = (o < OUT) ? o : 0;

    // per-half params in registers
    float a0[HIN], a1[HIN], a2[HIN], b0[HIN], b1[HIN], b2[HIN];
#pragma unroll
    for (int k = 0; k < HIN; k++) {
        int idx = (half * HIN + k) * OUT + oc;
        a0[k] = __ldg(&wh[idx]); a1[k] = __ldg(&wh[D + idx]); a2[k] = __ldg(&bh[idx]);
        b0[k] = __ldg(&wg[idx]); b1[k] = __ldg(&wg[D + idx]); b2[k] = __ldg(&bg[idx]);
    }

    int group = (blockIdx.x * THREADS + tid) >> 5;    // one warp per node
    int ng    = (GRID * THREADS) >> 5;

    for (int n = group; n < N; n += ng) {
        int r0 = __ldg(&g_rowptr[n]);
        int r1 = __ldg(&g_rowptr[n + 1]);
        float acc0 = 0.f, acc1 = 0.f;

        // depth-2 pipeline: next edge's metadata + x half-row prefetched
        int p = r0;
        int4 ep; float xc[HIN];
        if (p < r1) { ep = g_epack[p]; load_xhalf<IN>(xin, ep.y, half, xc); }
        while (p < r1) {
            int4 epn; float xnx[HIN];
            if (p + 1 < r1) { epn = g_epack[p + 1]; load_xhalf<IN>(xin, epn.y, half, xnx); }

            float ef0 = __int_as_float(ep.z), ef1 = __int_as_float(ep.w);
            const float2* eb = sE + ((ep.x * 16 + o) * 2 + half) * SLOT;
#pragma unroll
            for (int s = 0; s < HPAIR; s++) {
                float2 ev = eb[s];
                {
                    int k = 2 * s;
                    float hh = fmaf(ef0, a0[k], fmaf(ef1, a1[k], a2[k]));
                    float gg = fmaf(ef0, b0[k], fmaf(ef1, b1[k], b2[k]));
                    float w  = fmaxf(fmaf(ev.x, hh, gg), 0.f);
                    acc0 = fmaf(xc[k], w, acc0);
                }
                {
                    int k = 2 * s + 1;
                    float hh = fmaf(ef0, a0[k], fmaf(ef1, a1[k], a2[k]));
                    float gg = fmaf(ef0, b0[k], fmaf(ef1, b1[k], b2[k]));
                    float w  = fmaxf(fmaf(ev.y, hh, gg), 0.f);
                    acc1 = fmaf(xc[k], w, acc1);
                }
            }
            if (TAIL) {
                float2 ev = eb[HPAIR];
                int k = HIN - 1;
                float hh = fmaf(ef0, a0[k], fmaf(ef1, a1[k], a2[k]));
                float gg = fmaf(ef0, b0[k], fmaf(ef1, b1[k], b2[k]));
                float w  = fmaxf(fmaf(ev.x, hh, gg), 0.f);
                acc0 = fmaf(xc[k], w, acc0);
            }
            ep = epn;
#pragma unroll
            for (int k = 0; k < HIN; k++) xc[k] = xnx[k];
            p++;
        }

        // cross-half reduction of the message
        float m = acc0 + acc1;
        m += __shfl_xor_sync(0xffffffffu, m, 16);

        // root matmul: direct half-row load, then cross-half reduce
        float xk2[HIN];
        load_xhalf<IN>(xin, n, half, xk2);
        float r = 0.f;
#pragma unroll
        for (int k = 0; k < HIN; k++)
            r = fmaf(xk2[k], s_root[(half * HIN + k) * OUT + oc], r);
        r += __shfl_xor_sync(0xffffffffu, r, 16);

        int deg = r1 - r0;
        float inv = __frcp_rn((float)(deg > 0 ? deg : 1));
        float a = fmaxf(fmaf(m, inv, r + s_bias[oc]), 0.f);

        if (POOL) {
            if (half == 0) {
                if (__ldg(&ctype[n]) == 1) {
                    int b = __ldg(&bids[n]);
                    atomicAdd(&s_pool[b * 16 + o], a);
                    if (o == 0) atomicAdd(&s_cnt[b], 1);
                }
            }
        } else {
            if (half == 0 && o < OUT) hout[n * 16 + o] = a;
        }
    }

    if (POOL) {
        __syncthreads();
        if (tid < B * 16) {
            float v = s_pool[tid];
            if (v != 0.f) atomicAdd(&g_pool[tid], v);
        }
        if (tid < B) {
            int c = s_cnt[tid];
            if (c) atomicAdd(&g_pcnt[tid], c);
        }
    }
}

// ---------------------------------------------------------------- the single persistent kernel
__global__ __launch_bounds__(THREADS, 1)
void cellnet_kernel(KParams P)
{
    __shared__ float2 smbuf[4096];      // 32KB: union emb table (max 4000 float2) / scan buffers
    __shared__ float  s_root[256];
    __shared__ float  s_bias[16];
    __shared__ float  s_pool[128];
    __shared__ int    s_cnt[8];

    int tid  = threadIdx.x, bid = blockIdx.x;
    int gsz  = GRID * THREADS;
    int gtid = bid * THREADS + tid;
    int N = P.N, E = P.E;

    // ---- phase 0: zero histogram + pool state
    for (int j = gtid; j < N; j += gsz) g_rowcnt[j] = 0;
    if (bid == 0) {
        for (int j = tid; j < 64 * 16; j += THREADS) g_pool[j] = 0.f;
        if (tid < 64) g_pcnt[tid] = 0;
    }
    grid_barrier();

    // ---- phase 1: degree histogram
    for (int e = gtid; e < E; e += gsz) atomicAdd(&g_rowcnt[P.edst[e]], 1);
    grid_barrier();

    // ---- phase 2a: per-chunk sums (chunk = THREADS nodes -> block); pad to 1024 for the tree
    int nch = (N + THREADS - 1) / THREADS;           // 66 for N=50000
    int* sS = (int*)smbuf;
    if (bid < nch) {
        int n  = bid * THREADS + tid;
        int rc = (n < N) ? g_rowcnt[n] : 0;
        sS[tid] = rc;
        if (tid < 1024 - THREADS) sS[THREADS + tid] = 0;   // pad
        __syncthreads();
        for (int off = 512; off > 0; off >>= 1) {
            if (tid < off) sS[tid] += sS[tid + off];
            __syncthreads();
        }
        if (tid == 0) g_bsum[bid] = sS[0];
    }
    grid_barrier();

    // ---- phase 2b: rowptr = scan(bsum)[bid] + intra-chunk exclusive scan (Hillis-Steele)
    if (bid < nch) {
        int n  = bid * THREADS + tid;
        int rc = (n < N) ? g_rowcnt[n] : 0;
        int v  = (tid < nch) ? g_bsum[tid] : 0;
        sS[tid] = v; __syncthreads();
        for (int off = 1; off < THREADS; off <<= 1) {
            int u = (tid >= off) ? sS[tid - off] : 0;
            __syncthreads(); sS[tid] += u; __syncthreads();
        }
        int base = (bid == 0) ? 0 : sS[bid - 1];
        int* sT = sS + 1024;
        sT[tid] = rc; __syncthreads();
        for (int off = 1; off < THREADS; off <<= 1) {
            int u = (tid >= off) ? sT[tid - off] : 0;
            __syncthreads(); sT[tid] += u; __syncthreads();
        }
        int excl = sT[tid] - rc;
        if (n < N) {
            int st = base + excl;
            g_rowptr[n] = st;
            g_wcur[n]   = st;
            if (n == N - 1) g_rowptr[N] = E;
        }
    }
    grid_barrier();

    // ---- phase 3: scatter edges into CSR order
    for (int e = gtid; e < E; e += gsz) {
        int p = atomicAdd(&g_wcur[P.edst[e]], 1);
        float2 f = P.ef[e];
        g_epack[p] = make_int4(P.etype[e], P.esrc[e], __float_as_int(f.x), __float_as_int(f.y));
    }
    grid_barrier();

    // ---- phases 4-6: fused layers
    do_layer<16, 10, false>(P.x, g_h,
        P.emb[0], P.wh[0], P.bh[0], P.wg[0], P.bg[0], P.root[0], P.bias[0],
        nullptr, nullptr, smbuf, s_root, s_bias, s_pool, s_cnt, N, P.B);
    grid_barrier();

    do_layer<10, 10, false>(g_h, g_h2,
        P.emb[1], P.wh[1], P.bh[1], P.wg[1], P.bg[1], P.root[1], P.bias[1],
        nullptr, nullptr, smbuf, s_root, s_bias, s_pool, s_cnt, N, P.B);
    grid_barrier();

    do_layer<10, 16, true>(g_h2, nullptr,
        P.emb[2], P.wh[2], P.bh[2], P.wg[2], P.bg[2], P.root[2], P.bias[2],
        P.ctype, P.bids, smbuf, s_root, s_bias, s_pool, s_cnt, N, P.B);
    grid_barrier();

    // ---- phase 7: emit pooled means
    if (bid == 0 && tid < P.B * 16) {
        int b = tid >> 4;
        int c = g_pcnt[b];
        P.out[tid] = g_pool[tid] / (float)(c > 0 ? c : 1);
    }
}

// ---------------------------------------------------------------- launch
extern "C" void kernel_launch(void* const* d_in, const int* in_sizes, int n_in,
                              void* d_out, int out_size)
{
    bool setup_order = (in_sizes[2] == in_sizes[3]) && (in_sizes[3] == in_sizes[4]);

    KParams P;
    P.x  = (const float*)d_in[0];
    P.ef = (const float2*)d_in[1];
    int pbase, eidx, cidx;
    if (setup_order) {
        P.etype = (const int*)d_in[2];  P.esrc = (const int*)d_in[3];  P.edst = (const int*)d_in[4];
        P.ctype = (const int*)d_in[5];  P.bids = (const int*)d_in[6];
        pbase = 8; eidx = 2; cidx = 5;
    } else {
        P.etype = (const int*)d_in[23]; P.esrc = (const int*)d_in[24]; P.edst = (const int*)d_in[25];
        P.ctype = (const int*)d_in[26]; P.bids = (const int*)d_in[27];
        pbase = 2; eidx = 23; cidx = 26;
    }
    for (int l = 0; l < 3; l++) {
        int b0 = pbase + l * 7;
        P.emb[l]  = (const float*)d_in[b0];
        P.wh[l]   = (const float*)d_in[b0 + 1];
        P.bh[l]   = (const float*)d_in[b0 + 2];
        P.wg[l]   = (const float*)d_in[b0 + 3];
        P.bg[l]   = (const float*)d_in[b0 + 4];
        P.root[l] = (const float*)d_in[b0 + 5];
        P.bias[l] = (const float*)d_in[b0 + 6];
    }
    P.E = in_sizes[eidx];
    P.N = in_sizes[cidx];
    P.B = out_size / 16;
    P.out = (float*)d_out;

    cellnet_kernel<<<GRID, THREADS>>>(P);
}

// round 17
// speedup vs baseline: 1.0879x; 1.0879x over previous
#include <cuda_runtime.h>

#define NT   25
#define NMAX 50176
#define EMAX 250112
#define GRID 148
#define THREADS 896       // 28 warps/SM

__device__ float g_h [NMAX * 16];
__device__ float g_h2[NMAX * 16];
__device__ int   g_rowcnt[NMAX];
__device__ int   g_rowptr[NMAX + 1];
__device__ int   g_wcur  [NMAX];
__device__ int   g_bsum[512];
__device__ int4  g_epack[EMAX];       // CSR-ordered {etype, src, ef0_bits, ef1_bits}
__device__ float g_pool[64 * 16];
__device__ int   g_pcnt[64];
__device__ int   g_work[4];           // per-layer dynamic work counters

// ---- software grid barrier (sense-reversing)
__device__ unsigned g_count = 0;
__device__ volatile unsigned g_gen = 0;

__device__ __forceinline__ void grid_barrier() {
    __syncthreads();
    if (threadIdx.x == 0) {
        __threadfence();
        unsigned my = g_gen;
        if (atomicAdd(&g_count, 1u) == GRID - 1) {
            g_count = 0;
            __threadfence();
            g_gen = my + 1;
        } else {
            while (g_gen == my) __nanosleep(64);
        }
        __threadfence();
    }
    __syncthreads();
}

struct KParams {
    const float*  x;
    const float2* ef;
    const int *etype, *esrc, *edst, *ctype, *bids;
    const float *emb[3], *wh[3], *bh[3], *wg[3], *bg[3], *root[3], *bias[3];
    float* out;
    int N, E, B;
};

// ---- fused layer, 32-lane group per node, i-dim split across warp halves,
// depth-2 software pipeline, dynamic node queue (4-node chunks).
// w[t,i,o](ef) = relu(emb * (ef0*wh0 + ef1*wh1 + bh) + (ef0*wg0 + ef1*wg1 + bg))
template <int IN, int OUT, bool POOL>
__device__ __forceinline__ void do_layer(
    const float* __restrict__ xin, float* __restrict__ hout,
    const float* __restrict__ emb, const float* __restrict__ wh,
    const float* __restrict__ bh,  const float* __restrict__ wg,
    const float* __restrict__ bg,  const float* __restrict__ root,
    const float* __restrict__ bias,
    const int* __restrict__ ctype, const int* __restrict__ bids,
    float2* sE, float* s_root, float* s_bias,
    float* s_pool, int* s_cnt, int* wq, int N, int B)
{
    constexpr int D     = IN * OUT;
    constexpr int HIN   = IN / 2;                 // 8 or 5
    constexpr int HPAIR = HIN / 2;                // 4 or 2
    constexpr bool TAIL = (HIN & 1) != 0;         // IN=10 -> one tail step
    constexpr int SLOT  = (IN == 16) ? 5 : 3;     // padded float2 slots per (t,o,half)
    int tid = threadIdx.x;

    // emb table: sE[((t*16+o)*2+half)*SLOT + s] = (emb[t, half*HIN+2s, o], emb[t, half*HIN+2s+1, o])
    for (int j = tid; j < NT * 32 * SLOT; j += THREADS) {
        int s  = j % SLOT;
        int rh = j / SLOT;
        int hf = rh & 1;
        int o  = (rh >> 1) & 15;
        int t  = rh >> 5;
        int i0 = 2 * s;
        float e0 = 0.f, e1 = 0.f;
        if (o < OUT && i0 < HIN)     e0 = __ldg(&emb[t * D + (hf * HIN + i0)     * OUT + o]);
        if (o < OUT && i0 + 1 < HIN) e1 = __ldg(&emb[t * D + (hf * HIN + i0 + 1) * OUT + o]);
        sE[j] = make_float2(e0, e1);
    }
    if (tid < D)   s_root[tid] = __ldg(&root[tid]);
    if (tid < OUT) s_bias[tid] = __ldg(&bias[tid]);
    if (POOL) {
        if (tid < 128) s_pool[tid] = 0.f;
        if (tid < 8)   s_cnt[tid]  = 0;
    }
    __syncthreads();

    int o    = tid & 15;
    int half = (tid >> 4) & 1;
    int oc   = (o < OUT) ? o : 0;

    // per-half params in registers
    float a0[HIN], a1[HIN], a2[HIN], b0[HIN], b1[HIN], b2[HIN];
#pragma unroll
    for (int k = 0; k < HIN; k++) {
        int idx = (half * HIN + k) * OUT + oc;
        a0[k] = __ldg(&wh[idx]); a1[k] = __ldg(&wh[D + idx]); a2[k] = __ldg(&bh[idx]);
        b0[k] = __ldg(&wg[idx]); b1[k] = __ldg(&wg[D + idx]); b2[k] = __ldg(&bg[idx]);
    }

    // dynamic work queue: pull 4 contiguous nodes at a time (n0 initialized: no UB)
    bool done = false;
    while (!done) {
        int n0 = 0;
        if ((tid & 31) == 0) n0 = atomicAdd(wq, 4);
        n0 = __shfl_sync(0xffffffffu, n0, 0);
        if (n0 >= N) { done = true; break; }
        int nend = (n0 + 4 < N) ? n0 + 4 : N;

        for (int n = n0; n < nend; n++) {
            int r0 = __ldg(&g_rowptr[n]);
            int r1 = __ldg(&g_rowptr[n + 1]);
            float acc0 = 0.f, acc1 = 0.f;

            // depth-2 pipeline: next edge's metadata + x value prefetched
            int p = r0;
            int4 ep = make_int4(0, 0, 0, 0); float xv = 0.f;
            if (p < r1) { ep = g_epack[p]; xv = xin[ep.y * 16 + o]; }
            while (p < r1) {
                int4 epn = make_int4(0, 0, 0, 0); float xvn = 0.f;
                if (p + 1 < r1) { epn = g_epack[p + 1]; xvn = xin[epn.y * 16 + o]; }

                float ef0 = __int_as_float(ep.z), ef1 = __int_as_float(ep.w);
                const float2* eb = sE + ((ep.x * 16 + o) * 2 + half) * SLOT;
#pragma unroll
                for (int s = 0; s < HPAIR; s++) {
                    float2 ev = eb[s];
                    {
                        int k = 2 * s, i = half * HIN + k;
                        float hh = fmaf(ef0, a0[k], fmaf(ef1, a1[k], a2[k]));
                        float gg = fmaf(ef0, b0[k], fmaf(ef1, b1[k], b2[k]));
                        float w  = fmaxf(fmaf(ev.x, hh, gg), 0.f);
                        acc0 = fmaf(__shfl_sync(0xffffffffu, xv, i, 16), w, acc0);
                    }
                    {
                        int k = 2 * s + 1, i = half * HIN + k;
                        float hh = fmaf(ef0, a0[k], fmaf(ef1, a1[k], a2[k]));
                        float gg = fmaf(ef0, b0[k], fmaf(ef1, b1[k], b2[k]));
                        float w  = fmaxf(fmaf(ev.y, hh, gg), 0.f);
                        acc1 = fmaf(__shfl_sync(0xffffffffu, xv, i, 16), w, acc1);
                    }
                }
                if (TAIL) {
                    float2 ev = eb[HPAIR];
                    int k = HIN - 1, i = half * HIN + k;
                    float hh = fmaf(ef0, a0[k], fmaf(ef1, a1[k], a2[k]));
                    float gg = fmaf(ef0, b0[k], fmaf(ef1, b1[k], b2[k]));
                    float w  = fmaxf(fmaf(ev.x, hh, gg), 0.f);
                    acc0 = fmaf(__shfl_sync(0xffffffffu, xv, i, 16), w, acc0);
                }
                ep = epn; xv = xvn; p++;
            }

            // cross-half reduction of the message
            float m = acc0 + acc1;
            m += __shfl_xor_sync(0xffffffffu, m, 16);

            // root matmul: each half does its i-range, then reduce
            float xn = xin[n * 16 + o];
            float r = 0.f;
#pragma unroll
            for (int k = 0; k < HIN; k++) {
                int i = half * HIN + k;
                r = fmaf(__shfl_sync(0xffffffffu, xn, i, 16), s_root[i * OUT + oc], r);
            }
            r += __shfl_xor_sync(0xffffffffu, r, 16);

            int deg = r1 - r0;
            float inv = __frcp_rn((float)(deg > 0 ? deg : 1));
            float a = fmaxf(fmaf(m, inv, r + s_bias[oc]), 0.f);

            if (POOL) {
                if (half == 0) {
                    if (__ldg(&ctype[n]) == 1) {
                        int b = __ldg(&bids[n]);
                        atomicAdd(&s_pool[b * 16 + o], a);
                        if (o == 0) atomicAdd(&s_cnt[b], 1);
                    }
                }
            } else {
                if (half == 0 && o < OUT) hout[n * 16 + o] = a;
            }
        }
    }

    if (POOL) {
        __syncthreads();
        if (tid < B * 16) {
            float v = s_pool[tid];
            if (v != 0.f) atomicAdd(&g_pool[tid], v);
        }
        if (tid < B) {
            int c = s_cnt[tid];
            if (c) atomicAdd(&g_pcnt[tid], c);
        }
    }
}

// ---------------------------------------------------------------- the single persistent kernel
__global__ __launch_bounds__(THREADS, 1)
void cellnet_kernel(KParams P)
{
    __shared__ float2 smbuf[4096];      // 32KB: union emb table (max 4000 float2) / scan buffers
    __shared__ float  s_root[256];
    __shared__ float  s_bias[16];
    __shared__ float  s_pool[128];
    __shared__ int    s_cnt[8];

    int tid  = threadIdx.x, bid = blockIdx.x;
    int gsz  = GRID * THREADS;
    int gtid = bid * THREADS + tid;
    int N = P.N, E = P.E;

    // ---- phase 0: zero histogram + pool state + work counters
    for (int j = gtid; j < N; j += gsz) g_rowcnt[j] = 0;
    if (bid == 0) {
        for (int j = tid; j < 64 * 16; j += THREADS) g_pool[j] = 0.f;
        if (tid < 64) g_pcnt[tid] = 0;
        if (tid < 4)  g_work[tid] = 0;
    }
    grid_barrier();

    // ---- phase 1: degree histogram
    for (int e = gtid; e < E; e += gsz) atomicAdd(&g_rowcnt[P.edst[e]], 1);
    grid_barrier();

    // ---- phase 2a: per-chunk sums (chunk = THREADS nodes -> block); pad to 1024 for the tree
    int nch = (N + THREADS - 1) / THREADS;
    int* sS = (int*)smbuf;
    if (bid < nch) {
        int n  = bid * THREADS + tid;
        int rc = (n < N) ? g_rowcnt[n] : 0;
        sS[tid] = rc;
        if (tid < 1024 - THREADS) sS[THREADS + tid] = 0;   // pad
        __syncthreads();
        for (int off = 512; off > 0; off >>= 1) {
            if (tid < off) sS[tid] += sS[tid + off];
            __syncthreads();
        }
        if (tid == 0) g_bsum[bid] = sS[0];
    }
    grid_barrier();

    // ---- phase 2b: rowptr = scan(bsum)[bid] + intra-chunk exclusive scan (Hillis-Steele)
    if (bid < nch) {
        int n  = bid * THREADS + tid;
        int rc = (n < N) ? g_rowcnt[n] : 0;
        int v  = (tid < nch) ? g_bsum[tid] : 0;
        sS[tid] = v; __syncthreads();
        for (int off = 1; off < THREADS; off <<= 1) {
            int u = (tid >= off) ? sS[tid - off] : 0;
            __syncthreads(); sS[tid] += u; __syncthreads();
        }
        int base = (bid == 0) ? 0 : sS[bid - 1];
        int* sT = sS + 1024;
        sT[tid] = rc; __syncthreads();
        for (int off = 1; off < THREADS; off <<= 1) {
            int u = (tid >= off) ? sT[tid - off] : 0;
            __syncthreads(); sT[tid] += u; __syncthreads();
        }
        int excl = sT[tid] - rc;
        if (n < N) {
            int st = base + excl;
            g_rowptr[n] = st;
            g_wcur[n]   = st;
            if (n == N - 1) g_rowptr[N] = E;
        }
    }
    grid_barrier();

    // ---- phase 3: scatter edges into CSR order
    for (int e = gtid; e < E; e += gsz) {
        int p = atomicAdd(&g_wcur[P.edst[e]], 1);
        float2 f = P.ef[e];
        g_epack[p] = make_int4(P.etype[e], P.esrc[e], __float_as_int(f.x), __float_as_int(f.y));
    }
    grid_barrier();

    // ---- phases 4-6: fused layers (dynamic per-layer work queues)
    do_layer<16, 10, false>(P.x, g_h,
        P.emb[0], P.wh[0], P.bh[0], P.wg[0], P.bg[0], P.root[0], P.bias[0],
        nullptr, nullptr, smbuf, s_root, s_bias, s_pool, s_cnt, &g_work[0], N, P.B);
    grid_barrier();

    do_layer<10, 10, false>(g_h, g_h2,
        P.emb[1], P.wh[1], P.bh[1], P.wg[1], P.bg[1], P.root[1], P.bias[1],
        nullptr, nullptr, smbuf, s_root, s_bias, s_pool, s_cnt, &g_work[1], N, P.B);
    grid_barrier();

    do_layer<10, 16, true>(g_h2, nullptr,
        P.emb[2], P.wh[2], P.bh[2], P.wg[2], P.bg[2], P.root[2], P.bias[2],
        P.ctype, P.bids, smbuf, s_root, s_bias, s_pool, s_cnt, &g_work[2], N, P.B);
    grid_barrier();

    // ---- phase 7: emit pooled means
    if (bid == 0 && tid < P.B * 16) {
        int b = tid >> 4;
        int c = g_pcnt[b];
        P.out[tid] = g_pool[tid] / (float)(c > 0 ? c : 1);
    }
}

// ---------------------------------------------------------------- launch
extern "C" void kernel_launch(void* const* d_in, const int* in_sizes, int n_in,
                              void* d_out, int out_size)
{
    bool setup_order = (in_sizes[2] == in_sizes[3]) && (in_sizes[3] == in_sizes[4]);

    KParams P;
    P.x  = (const float*)d_in[0];
    P.ef = (const float2*)d_in[1];
    int pbase, eidx, cidx;
    if (setup_order) {
        P.etype = (const int*)d_in[2];  P.esrc = (const int*)d_in[3];  P.edst = (const int*)d_in[4];
        P.ctype = (const int*)d_in[5];  P.bids = (const int*)d_in[6];
        pbase = 8; eidx = 2; cidx = 5;
    } else {
        P.etype = (const int*)d_in[23]; P.esrc = (const int*)d_in[24]; P.edst = (const int*)d_in[25];
        P.ctype = (const int*)d_in[26]; P.bids = (const int*)d_in[27];
        pbase = 2; eidx = 23; cidx = 26;
    }
    for (int l = 0; l < 3; l++) {
        int b0 = pbase + l * 7;
        P.emb[l]  = (const float*)d_in[b0];
        P.wh[l]   = (const float*)d_in[b0 + 1];
        P.bh[l]   = (const float*)d_in[b0 + 2];
        P.wg[l]   = (const float*)d_in[b0 + 3];
        P.bg[l]   = (const float*)d_in[b0 + 4];
        P.root[l] = (const float*)d_in[b0 + 5];
        P.bias[l] = (const float*)d_in[b0 + 6];
    }
    P.E = in_sizes[eidx];
    P.N = in_sizes[cidx];
    P.B = out_size / 16;
    P.out = (float*)d_out;

    cellnet_kernel<<<GRID, THREADS>>>(P);
}